// round 17
// baseline (speedup 1.0000x reference)
#include <cuda_runtime.h>
#include <cuda_fp16.h>
#include <cfloat>
#include <cstdint>

#define BB 8
#define CC 3
#define HH 1080
#define WW 1920
#define KK 256
#define NBASIS 25
#define GBINS 4096              // bins centered at g/4096, width 1/4096 (magic-RN)
#define NBINS 4097              // g in [0, 4096]
#define NBINS_PAD 4100
#define NSEG (KK + 1)           // 257 extended segments
#define PIX_PER_BATCH (CC * HH * WW)   // 6,220,800
#define NF4 (PIX_PER_BATCH / 4)        // 1,555,200
#define GX 148                          // blocks per batch: 148*8 = 1184 CTAs
#define STRIDE (GX * 256)               // 37,888
#define MAGIC 8388608.0f                // 2^23

// ---------------------------------------------------------------------------
// Fast path: magic-RN index (no CVT), LDS.32, paired F2F extraction,
// center+delta lerp. Kinked bins carry an fp16 NaN center -> y is NaN ->
// single FSETP routes to the exact fp32 segment walk.
// ---------------------------------------------------------------------------
__device__ __forceinline__ float tmo_eval(float x, const uint32_t* sBins,
                                          const float* sHi, const float2* sAB) {
    float s = fmaf(x, 4096.0f, MAGIC);          // RN -> integer g in mantissa
    int g = __float_as_int(s) & 0x1FFF;         // g in [0, 4096]
    float gf = s - MAGIC;                       // exact (Sterbenz)
    float frac = fmaf(x, 4096.0f, -gf);         // exact, in [-0.5, 0.5]
    uint32_t u = sBins[g];
    float2 f = __half22float2(*reinterpret_cast<const __half2*>(&u));  // (yc, dy)
    float y = fmaf(f.y, frac, f.x);
    if (!(y == y)) {                            // NaN => kinked bin
        int k = (int)(u & 0x3FFu) - 1;
        while (x >= sHi[k]) k++;
        float2 ab = sAB[k];
        y = fmaf(ab.x, x, ab.y);
    }
    return __saturatef(y);
}

// ---------------------------------------------------------------------------
// Fused kernel: each block builds the per-batch tables in shared (no global
// round-trip, no second launch), then streams its slice of pixels.
// Grid (148, 8) = 1184 blocks = one uniform wave at 8 CTAs/SM (~21.4 KB smem).
// ---------------------------------------------------------------------------
__global__ void __launch_bounds__(256, 8)
tmo_fused(const float* __restrict__ img, float* __restrict__ out,
          const float* __restrict__ w,  const float* __restrict__ E,
          const float* __restrict__ f0, const float* __restrict__ Hb) {
    __shared__ uint32_t sBins[NBINS_PAD];   // 16.0 KB
    __shared__ float    sHi[NSEG];          // ~1 KB
    __shared__ float2   sAB[NSEG];          // ~2 KB
    __shared__ float    sE[KK];             // 1 KB
    __shared__ float    sC[KK];             // 1 KB

    const int b = blockIdx.y;
    const int t = threadIdx.x;

    // ---- 1. per-batch curve (identical arithmetic to the old builder) ----
    {
        float acc = f0[t];
        #pragma unroll
        for (int n = 0; n < NBASIS; n++)
            acc = fmaf(Hb[t * NBASIS + n], w[b * NBASIS + n], acc);
        sE[t] = E[t];
        sC[t] = acc;
    }
    __syncthreads();

    // ---- 2. segment table (t covers k=t; t==0 also covers k=256) ----
    for (int k = t; k < NSEG; k += 256) {
        float hi; float2 ab;
        if (k == 0) {
            hi = sE[0];            ab = make_float2(0.0f, sC[0]);
        } else if (k == KK) {
            hi = FLT_MAX;          ab = make_float2(0.0f, sC[KK - 1]);
        } else {
            float a = (sC[k] - sC[k - 1]) / (sE[k] - sE[k - 1]);
            hi = sE[k];            ab = make_float2(a, fmaf(-a, sE[k - 1], sC[k - 1]));
        }
        sHi[k] = hi;
        sAB[k] = ab;
    }

    // ---- 3. bin table: 16 consecutive bins per thread, one search + walk ----
    {
        const int g0 = t * 16;
        const int gend = (t == 255) ? NBINS : g0 + 16;   // thread 255 takes g=4096 too

        // k = #E <= left(g0)   (same definition as the old per-bin search)
        float left0 = (float)(2 * g0 - 1) * (1.0f / 8192.0f);
        int lo = 0, hi = KK;
        while (lo < hi) {
            int mid = (lo + hi) >> 1;
            if (sE[mid] <= left0) lo = mid + 1; else hi = mid;
        }
        int k = lo;

        float ca = 0.0f, cb = 0.0f;   // cached line of segment ck
        int ck = -1;

        for (int g = g0; g < gend; g++) {
            float left  = (float)(2 * g - 1) * (1.0f / 8192.0f);  // exact
            float right = (float)(2 * g + 1) * (1.0f / 8192.0f);  // exact
            while (k < KK && sE[k] <= left) k++;
            float upper = (k < KK) ? sE[k] : FLT_MAX;
            uint32_t u;
            if (upper >= right) {
                float yc, dy;
                if (k == 0) {
                    yc = sC[0];          dy = 0.0f;
                } else if (k == KK) {
                    yc = sC[KK - 1];     dy = 0.0f;
                } else {
                    if (ck != k) {       // same expressions as old builder
                        ca = (sC[k] - sC[k - 1]) / (sE[k] - sE[k - 1]);
                        cb = fmaf(-ca, sE[k - 1], sC[k - 1]);
                        ck = k;
                    }
                    float xc = (float)g * (1.0f / 4096.0f);       // exact
                    yc = fmaf(ca, xc, cb);
                    dy = ca * (1.0f / 4096.0f);
                }
                uint16_t hc = __half_as_ushort(__float2half_rn(yc));
                uint16_t hd = __half_as_ushort(__float2half_rn(dy));
                u = ((uint32_t)hd << 16) | hc;     // finite halfs: never NaN-pattern
            } else {
                u = 0x7C000000u | (0x7C00u | (uint32_t)(k + 1));  // NaN sentinel + payload
            }
            sBins[g] = u;
        }
    }
    __syncthreads();

    // ---- 4. streaming apply (identical to the R11/R16 champion loop) ----
    const float4* in4  = reinterpret_cast<const float4*>(img + (size_t)b * PIX_PER_BATCH);
    float4*       out4 = reinterpret_cast<float4*>(out + (size_t)b * PIX_PER_BATCH);

    int i = blockIdx.x * blockDim.x + t;   // < STRIDE <= NF4, so >=1 elem

    float4 v = in4[i];
    int nxt = i + STRIDE;

    #pragma unroll 1
    while (nxt < NF4) {
        float4 vn = in4[nxt];            // prefetch: overlaps with processing below
        float4 r;
        r.x = tmo_eval(v.x, sBins, sHi, sAB);
        r.y = tmo_eval(v.y, sBins, sHi, sAB);
        r.z = tmo_eval(v.z, sBins, sHi, sAB);
        r.w = tmo_eval(v.w, sBins, sHi, sAB);
        out4[i] = r;
        v = vn;
        i = nxt;
        nxt += STRIDE;
    }
    {
        float4 r;
        r.x = tmo_eval(v.x, sBins, sHi, sAB);
        r.y = tmo_eval(v.y, sBins, sHi, sAB);
        r.z = tmo_eval(v.z, sBins, sHi, sAB);
        r.w = tmo_eval(v.w, sBins, sHi, sAB);
        out4[i] = r;
    }
}

extern "C" void kernel_launch(void* const* d_in, const int* in_sizes, int n_in,
                              void* d_out, int out_size) {
    const float* hdr = (const float*)d_in[0];   // [B,C,H,W]
    const float* w   = (const float*)d_in[1];   // [B,NB]
    const float* E   = (const float*)d_in[2];   // [K]
    const float* f0  = (const float*)d_in[3];   // [K]
    const float* Hb  = (const float*)d_in[4];   // [K,NB]
    float* out = (float*)d_out;

    dim3 grid(GX, BB);   // 1184 blocks = single uniform wave at 8 CTAs/SM
    tmo_fused<<<grid, 256>>>(hdr, out, w, E, f0, Hb);
}